// round 6
// baseline (speedup 1.0000x reference)
#include <cuda_runtime.h>

#define DD 128
#define NMAX 40000
#define ASTRIDE 65   // padded k-major A tile stride; NOTE: only scalar LDS on As (65*4 % 16 != 0)

// ---------------- device scratch (no allocs allowed), 16B-aligned ----------------
__device__ __align__(16) float g_delta[(size_t)NMAX * 3];
__device__ __align__(16) float g_xf[(size_t)NMAX * DD];
__device__ __align__(16) float g_aggr[(size_t)NMAX * DD];
__device__ int   g_is64;

__device__ __forceinline__ float lrelu(float v) { return v >= 0.f ? v : 0.01f * v; }

__device__ __forceinline__ void red_add_v4(float* addr, float4 v) {
    asm volatile("red.global.add.v4.f32 [%0], {%1,%2,%3,%4};"
                 :: "l"(addr), "f"(v.x), "f"(v.y), "f"(v.z), "f"(v.w) : "memory");
}

// scalar (4B-safe) smem fill of a 128x128 weight matrix, 256 threads
__device__ __forceinline__ void fill_w(float* Bs, const float* __restrict__ W, int tid) {
    #pragma unroll
    for (int i = 0; i < 64; i++) Bs[tid + (i << 8)] = __ldg(W + tid + (i << 8));
}

// ---------------- edge_index dtype sniffer ----------------
__global__ void detect_idx_kernel(const unsigned int* ei32, int E_) {
    __shared__ int ok;
    if (threadIdx.x == 0) ok = 1;
    __syncthreads();
    if (E_ > 0) {
        long long stride = (long long)E_ / 256;
        if (stride < 1) stride = 1;
        long long i = (long long)threadIdx.x * stride;   // i < E_
        if (i < E_) {
            unsigned int hi = ei32[2 * i + 1];
            if (hi != 0) ok = 0;
        }
    }
    __syncthreads();
    if (threadIdx.x == 0) g_is64 = ok;
}

// 64x128x128 GEMM inner loop: A k-major [128][ASTRIDE] (scalar broadcast loads),
// B row-major [128][128] (float4 loads), 8x4 accum per thread.
__device__ __forceinline__ void gemm_64(const float* __restrict__ As,
                                        const float* __restrict__ Bs,
                                        int r0, int col0, float acc[8][4]) {
    #pragma unroll
    for (int i = 0; i < 8; i++)
        #pragma unroll
        for (int j = 0; j < 4; j++) acc[i][j] = 0.f;

    #pragma unroll 8
    for (int k = 0; k < 128; k++) {
        float4 b = *(const float4*)(Bs + k * 128 + col0);   // aligned: 128-float stride
        const float* ap = As + k * ASTRIDE + r0;            // warp-uniform -> broadcast
        float a[8];
        #pragma unroll
        for (int j = 0; j < 8; j++) a[j] = ap[j];           // scalar LDS.32 (alignment-safe)
        #pragma unroll
        for (int i = 0; i < 8; i++) {
            acc[i][0] = fmaf(a[i], b.x, acc[i][0]);
            acc[i][1] = fmaf(a[i], b.y, acc[i][1]);
            acc[i][2] = fmaf(a[i], b.z, acc[i][2]);
            acc[i][3] = fmaf(a[i], b.w, acc[i][3]);
        }
    }
}

// ---------------- fused node precompute: h, delta, xf ----------------
__global__ void __launch_bounds__(256) node_pre(
    const float* __restrict__ x,
    const float* __restrict__ Wh1, const float* __restrict__ bh1,
    const float* __restrict__ Wh2, const float* __restrict__ bh2,
    const float* __restrict__ Wf1, const float* __restrict__ bf1,
    int n)
{
    extern __shared__ float sm[];
    float* As = sm;                               // 128*ASTRIDE
    float* Bs = sm + 128 * ASTRIDE;               // 128*128
    float* Hs = sm + 128 * ASTRIDE + 128 * 128;   // 64*129
    const int tid  = threadIdx.x;
    const int row0 = blockIdx.x * 64;

    // load x tile transposed into k-major As — scalar global loads
    {
        const int r  = tid >> 5;          // 0..7
        const int k4 = (tid & 31) << 2;   // k offset
        #pragma unroll
        for (int i = 0; i < 8; i++) {
            int row  = r + (i << 3);
            int grow = row0 + row; if (grow >= n) grow = n - 1;
            const float* xp = x + (size_t)grow * DD + k4;
            As[(k4 + 0) * ASTRIDE + row] = __ldg(xp + 0);
            As[(k4 + 1) * ASTRIDE + row] = __ldg(xp + 1);
            As[(k4 + 2) * ASTRIDE + row] = __ldg(xp + 2);
            As[(k4 + 3) * ASTRIDE + row] = __ldg(xp + 3);
        }
    }
    fill_w(Bs, Wh1, tid);
    __syncthreads();

    const int col0 = (tid & 31) << 2;   // lanes sweep columns -> conflict-free B
    const int r0   = (tid >> 5) << 3;   // warp-uniform rows -> broadcast A

    // ---- GEMM1: h = leaky(x @ Wh1 + bh1) ----
    float acc[8][4];
    gemm_64(As, Bs, r0, col0, acc);
    {
        float b0 = __ldg(bh1 + col0 + 0), b1 = __ldg(bh1 + col0 + 1);
        float b2 = __ldg(bh1 + col0 + 2), b3 = __ldg(bh1 + col0 + 3);
        #pragma unroll
        for (int i = 0; i < 8; i++) {
            float* hp = Hs + (r0 + i) * 129 + col0;
            hp[0] = lrelu(acc[i][0] + b0);
            hp[1] = lrelu(acc[i][1] + b1);
            hp[2] = lrelu(acc[i][2] + b2);
            hp[3] = lrelu(acc[i][3] + b3);
        }
    }
    __syncthreads();

    // reload Bs with Wf1 rows 3..130 (x-part of Wf1)
    fill_w(Bs, Wf1 + 3 * DD, tid);

    // delta = tanh(h @ Wh2 + bh2), 64 rows x 3 cols
    if (tid < 192) {
        int row = tid / 3, c = tid - row * 3;
        float s = __ldg(bh2 + c);
        const float* hrow = Hs + row * 129;
        #pragma unroll 4
        for (int k = 0; k < 128; k++) s = fmaf(hrow[k], __ldg(Wh2 + k * 3 + c), s);
        int grow = row0 + row;
        if (grow < n) g_delta[(size_t)grow * 3 + c] = tanhf(s);
    }
    __syncthreads();

    // ---- GEMM2: xf = x @ Wf1[3:] + bf1 (pre-activation) ----
    gemm_64(As, Bs, r0, col0, acc);
    {
        float b0 = __ldg(bf1 + col0 + 0), b1 = __ldg(bf1 + col0 + 1);
        float b2 = __ldg(bf1 + col0 + 2), b3 = __ldg(bf1 + col0 + 3);
        #pragma unroll
        for (int i = 0; i < 8; i++) {
            int grow = row0 + r0 + i;
            if (grow < n) {
                float4 o;
                o.x = acc[i][0] + b0;
                o.y = acc[i][1] + b1;
                o.z = acc[i][2] + b2;
                o.w = acc[i][3] + b3;
                *(float4*)(g_xf + (size_t)grow * DD + col0) = o;   // g_xf __align__(16), col0%4==0
            }
        }
    }
}

// ---------------- edge kernel: warp per edge ----------------
__global__ void __launch_bounds__(256) edge_kernel(
    const void* __restrict__ ei_raw, const float* __restrict__ pos,
    const float* __restrict__ Wf1, int E_)
{
    __shared__ float w[3 * DD];
    if (threadIdx.x < 128) {
        w[threadIdx.x]       = __ldg(Wf1 + threadIdx.x);
        w[128 + threadIdx.x] = __ldg(Wf1 + DD + threadIdx.x);
        w[256 + threadIdx.x] = __ldg(Wf1 + 2 * DD + threadIdx.x);
    }
    __syncthreads();

    int gw = (blockIdx.x * 256 + threadIdx.x) >> 5;
    if (gw >= E_) return;
    const int lane = threadIdx.x & 31;

    int src, dst;
    if (g_is64) {
        const long long* ei = (const long long*)ei_raw;
        src = (int)ei[gw];
        dst = (int)ei[(size_t)E_ + gw];
    } else {
        const int* ei = (const int*)ei_raw;
        src = ei[gw];
        dst = ei[(size_t)E_ + gw];
    }

    float r0 = __ldg(pos + src * 3 + 0) - __ldg(pos + dst * 3 + 0) + g_delta[dst * 3 + 0];
    float r1 = __ldg(pos + src * 3 + 1) - __ldg(pos + dst * 3 + 1) + g_delta[dst * 3 + 1];
    float r2 = __ldg(pos + src * 3 + 2) - __ldg(pos + dst * 3 + 2) + g_delta[dst * 3 + 2];

    const int c = lane << 2;
    float4 xv = *(const float4*)(g_xf + (size_t)src * DD + c);   // aligned device array
    float4 m;
    m.x = lrelu(fmaf(r0, w[c + 0], fmaf(r1, w[128 + c + 0], fmaf(r2, w[256 + c + 0], xv.x))));
    m.y = lrelu(fmaf(r0, w[c + 1], fmaf(r1, w[128 + c + 1], fmaf(r2, w[256 + c + 1], xv.y))));
    m.z = lrelu(fmaf(r0, w[c + 2], fmaf(r1, w[128 + c + 2], fmaf(r2, w[256 + c + 2], xv.z))));
    m.w = lrelu(fmaf(r0, w[c + 3], fmaf(r1, w[128 + c + 3], fmaf(r2, w[256 + c + 3], xv.w))));

    red_add_v4(g_aggr + (size_t)dst * DD + c, m);                // aligned device array
}

// ---------------- fused node post: out = x + leaky(aggr@Wg1+bg1)@Wg2 + bg2 ----------------
__global__ void __launch_bounds__(256) node_post(
    const float* __restrict__ x,
    const float* __restrict__ Wg1, const float* __restrict__ bg1,
    const float* __restrict__ Wg2, const float* __restrict__ bg2,
    float* __restrict__ out, int n)
{
    extern __shared__ float sm[];
    float* As = sm;                    // 128*ASTRIDE
    float* Bs = sm + 128 * ASTRIDE;    // 128*128
    const int tid  = threadIdx.x;
    const int row0 = blockIdx.x * 64;

    // load aggr tile transposed (aligned device array -> float4 OK)
    {
        const int r  = tid >> 5;
        const int k4 = (tid & 31) << 2;
        #pragma unroll
        for (int i = 0; i < 8; i++) {
            int row  = r + (i << 3);
            int grow = row0 + row; if (grow >= n) grow = n - 1;
            float4 v = *(const float4*)(g_aggr + (size_t)grow * DD + k4);
            As[(k4 + 0) * ASTRIDE + row] = v.x;
            As[(k4 + 1) * ASTRIDE + row] = v.y;
            As[(k4 + 2) * ASTRIDE + row] = v.z;
            As[(k4 + 3) * ASTRIDE + row] = v.w;
        }
    }
    fill_w(Bs, Wg1, tid);
    __syncthreads();

    const int col0 = (tid & 31) << 2;
    const int r0   = (tid >> 5) << 3;

    float acc[8][4];
    gemm_64(As, Bs, r0, col0, acc);
    __syncthreads();  // done reading As before overwriting with t

    // t = leaky(acc + bg1) stored k-major back into As for GEMM2
    {
        float b0 = __ldg(bg1 + col0 + 0), b1 = __ldg(bg1 + col0 + 1);
        float b2 = __ldg(bg1 + col0 + 2), b3 = __ldg(bg1 + col0 + 3);
        #pragma unroll
        for (int i = 0; i < 8; i++) {
            As[(col0 + 0) * ASTRIDE + r0 + i] = lrelu(acc[i][0] + b0);
            As[(col0 + 1) * ASTRIDE + r0 + i] = lrelu(acc[i][1] + b1);
            As[(col0 + 2) * ASTRIDE + r0 + i] = lrelu(acc[i][2] + b2);
            As[(col0 + 3) * ASTRIDE + r0 + i] = lrelu(acc[i][3] + b3);
        }
    }
    fill_w(Bs, Wg2, tid);
    __syncthreads();

    gemm_64(As, Bs, r0, col0, acc);
    {
        float b0 = __ldg(bg2 + col0 + 0), b1 = __ldg(bg2 + col0 + 1);
        float b2 = __ldg(bg2 + col0 + 2), b3 = __ldg(bg2 + col0 + 3);
        #pragma unroll
        for (int i = 0; i < 8; i++) {
            int grow = row0 + r0 + i;
            if (grow < n) {
                const float* xp = x + (size_t)grow * DD + col0;
                float* op = out + (size_t)grow * DD + col0;
                op[0] = __ldg(xp + 0) + acc[i][0] + b0;
                op[1] = __ldg(xp + 1) + acc[i][1] + b1;
                op[2] = __ldg(xp + 2) + acc[i][2] + b2;
                op[3] = __ldg(xp + 3) + acc[i][3] + b3;
            }
        }
    }
}

// ---------------- launch ----------------
extern "C" void kernel_launch(void* const* d_in, const int* in_sizes, int n_in,
                              void* d_out, int out_size)
{
    const float* x   = (const float*)d_in[0];
    const float* pos = (const float*)d_in[1];
    const void*  ei  = d_in[2];
    const float* Wh1 = (const float*)d_in[3];
    const float* bh1 = (const float*)d_in[4];
    const float* Wh2 = (const float*)d_in[5];
    const float* bh2 = (const float*)d_in[6];
    const float* Wf1 = (const float*)d_in[7];
    const float* bf1 = (const float*)d_in[8];
    const float* Wg1 = (const float*)d_in[9];
    const float* bg1 = (const float*)d_in[10];
    const float* Wg2 = (const float*)d_in[11];
    const float* bg2 = (const float*)d_in[12];
    float* out = (float*)d_out;

    const int n  = in_sizes[0] / DD;
    const int E_ = in_sizes[2] / 2;

    const int PRE_SMEM  = (128 * ASTRIDE + 128 * 128 + 64 * 129) * (int)sizeof(float);
    const int POST_SMEM = (128 * ASTRIDE + 128 * 128) * (int)sizeof(float);
    cudaFuncSetAttribute(node_pre,  cudaFuncAttributeMaxDynamicSharedMemorySize, PRE_SMEM);
    cudaFuncSetAttribute(node_post, cudaFuncAttributeMaxDynamicSharedMemorySize, POST_SMEM);

    void* aggrPtr = nullptr;
    cudaGetSymbolAddress(&aggrPtr, g_aggr);
    cudaMemsetAsync(aggrPtr, 0, (size_t)n * DD * sizeof(float));

    detect_idx_kernel<<<1, 256>>>((const unsigned int*)ei, E_);

    const int gridN = (n + 63) / 64;
    node_pre<<<gridN, 256, PRE_SMEM>>>(x, Wh1, bh1, Wh2, bh2, Wf1, bf1, n);
    edge_kernel<<<(E_ + 7) / 8, 256>>>(ei, pos, Wf1, E_);
    node_post<<<gridN, 256, POST_SMEM>>>(x, Wg1, bg1, Wg2, bg2, out, n);
}

// round 7
// speedup vs baseline: 1.1848x; 1.1848x over previous
#include <cuda_runtime.h>

#define DD 128
#define NMAX 40000
#define ASR 132   // row-major A tile stride: 132*4=528 bytes, 16B-aligned float4 rows

// ---------------- device scratch (no allocs allowed), 16B-aligned ----------------
__device__ __align__(16) float g_delta[(size_t)NMAX * 3];
__device__ __align__(16) float g_xf[(size_t)NMAX * DD];
__device__ __align__(16) float g_aggr[(size_t)NMAX * DD];
__device__ int   g_is64;

__device__ __forceinline__ float lrelu(float v) { return v >= 0.f ? v : 0.01f * v; }

__device__ __forceinline__ void red_add_v4(float* addr, float4 v) {
    asm volatile("red.global.add.v4.f32 [%0], {%1,%2,%3,%4};"
                 :: "l"(addr), "f"(v.x), "f"(v.y), "f"(v.z), "f"(v.w) : "memory");
}

// packed f32x2 helpers (Blackwell FFMA2 path)
__device__ __forceinline__ unsigned long long pack2(float v) {
    unsigned long long r;
    asm("mov.b64 %0, {%1, %1};" : "=l"(r) : "f"(v));
    return r;
}
__device__ __forceinline__ void ffma2(unsigned long long& d, unsigned long long a,
                                      unsigned long long b) {
    asm("fma.rn.f32x2 %0, %1, %2, %0;" : "+l"(d) : "l"(a), "l"(b));
}
__device__ __forceinline__ float2 unpack2(unsigned long long u) {
    float2 f;
    asm("mov.b64 {%0, %1}, %2;" : "=f"(f.x), "=f"(f.y) : "l"(u));
    return f;
}

// scalar (4B-safe) smem fill of a 128x128 weight matrix, 256 threads
__device__ __forceinline__ void fill_w(float* Bs, const float* __restrict__ W, int tid) {
    #pragma unroll
    for (int i = 0; i < 64; i++) Bs[tid + (i << 8)] = __ldg(W + tid + (i << 8));
}

// ---------------- edge_index dtype sniffer ----------------
__global__ void detect_idx_kernel(const unsigned int* ei32, int E_) {
    __shared__ int ok;
    if (threadIdx.x == 0) ok = 1;
    __syncthreads();
    if (E_ > 0) {
        long long stride = (long long)E_ / 256;
        if (stride < 1) stride = 1;
        long long i = (long long)threadIdx.x * stride;   // i < E_
        if (i < E_) {
            unsigned int hi = ei32[2 * i + 1];
            if (hi != 0) ok = 0;
        }
    }
    __syncthreads();
    if (threadIdx.x == 0) g_is64 = ok;
}

// 64x128x128 GEMM: A row-major [64][ASR] (float4 broadcast loads),
// B row-major [128][128] (ulonglong2 loads), FFMA2 accumulation.
// acc2[i][0] = cols (col0,col0+1), acc2[i][1] = cols (col0+2,col0+3) for row r0+i.
__device__ __forceinline__ void gemm_64_f32x2(const float* __restrict__ As,
                                              const float* __restrict__ Bs,
                                              int r0, int col0,
                                              unsigned long long acc2[8][2]) {
    #pragma unroll
    for (int i = 0; i < 8; i++) { acc2[i][0] = 0ull; acc2[i][1] = 0ull; }

    #pragma unroll 4
    for (int kk = 0; kk < 128; kk += 4) {
        ulonglong2 b[4];
        #pragma unroll
        for (int j = 0; j < 4; j++)
            b[j] = *(const ulonglong2*)(Bs + (kk + j) * 128 + col0);   // 16B-aligned
        #pragma unroll
        for (int i = 0; i < 8; i++) {
            float4 av = *(const float4*)(As + (r0 + i) * ASR + kk);    // broadcast, aligned
            unsigned long long a0 = pack2(av.x), a1 = pack2(av.y);
            unsigned long long a2 = pack2(av.z), a3 = pack2(av.w);
            ffma2(acc2[i][0], a0, b[0].x); ffma2(acc2[i][1], a0, b[0].y);
            ffma2(acc2[i][0], a1, b[1].x); ffma2(acc2[i][1], a1, b[1].y);
            ffma2(acc2[i][0], a2, b[2].x); ffma2(acc2[i][1], a2, b[2].y);
            ffma2(acc2[i][0], a3, b[3].x); ffma2(acc2[i][1], a3, b[3].y);
        }
    }
}

// ---------------- fused node precompute: h, delta, xf ----------------
// smem: As[64][ASR] (row-major x tile), Bs[128][128] (weights; Hs aliases Bs between GEMMs)
__global__ void __launch_bounds__(256) node_pre(
    const float* __restrict__ x,
    const float* __restrict__ Wh1, const float* __restrict__ bh1,
    const float* __restrict__ Wh2, const float* __restrict__ bh2,
    const float* __restrict__ Wf1, const float* __restrict__ bf1,
    int n)
{
    extern __shared__ float sm[];
    float* As = sm;                 // 64*ASR
    float* Bs = sm + 64 * ASR;      // 128*128 (Hs[64][129] aliases its head between GEMMs)
    const int tid  = threadIdx.x;
    const int row0 = blockIdx.x * 64;

    // load x tile row-major (x = d_in[0], base-aligned -> float4 OK)
    {
        const int row  = tid >> 2;
        const int cb   = (tid & 3) << 2;   // 0,4,8,12
        int grow = row0 + row; if (grow >= n) grow = n - 1;
        #pragma unroll
        for (int i = 0; i < 8; i++) {
            int col = cb + (i << 4);
            float4 v = *(const float4*)(x + (size_t)grow * DD + col);
            *(float4*)(As + row * ASR + col) = v;
        }
    }
    fill_w(Bs, Wh1, tid);
    __syncthreads();

    const int col0 = (tid & 31) << 2;
    const int r0   = (tid >> 5) << 3;

    // ---- GEMM1: h = leaky(x @ Wh1 + bh1) ----
    unsigned long long acc2[8][2];
    gemm_64_f32x2(As, Bs, r0, col0, acc2);
    __syncthreads();   // everyone done reading Bs (Wh1) before Hs overwrite

    float* Hs = Bs;    // [64][129]
    {
        float b0 = __ldg(bh1 + col0 + 0), b1 = __ldg(bh1 + col0 + 1);
        float b2 = __ldg(bh1 + col0 + 2), b3 = __ldg(bh1 + col0 + 3);
        #pragma unroll
        for (int i = 0; i < 8; i++) {
            float2 c01 = unpack2(acc2[i][0]);
            float2 c23 = unpack2(acc2[i][1]);
            float* hp = Hs + (r0 + i) * 129 + col0;
            hp[0] = lrelu(c01.x + b0);
            hp[1] = lrelu(c01.y + b1);
            hp[2] = lrelu(c23.x + b2);
            hp[3] = lrelu(c23.y + b3);
        }
    }
    __syncthreads();

    // delta = tanh(h @ Wh2 + bh2), 64 rows x 3 cols
    if (tid < 192) {
        int row = tid / 3, c = tid - row * 3;
        float s = __ldg(bh2 + c);
        const float* hrow = Hs + row * 129;
        #pragma unroll 4
        for (int k = 0; k < 128; k++) s = fmaf(hrow[k], __ldg(Wh2 + k * 3 + c), s);
        int grow = row0 + row;
        if (grow < n) g_delta[(size_t)grow * 3 + c] = tanhf(s);
    }
    __syncthreads();

    // refill Bs with Wf1 rows 3..130 (x-part of Wf1; only 4B-aligned -> scalar fill)
    fill_w(Bs, Wf1 + 3 * DD, tid);
    __syncthreads();

    // ---- GEMM2: xf = x @ Wf1[3:] + bf1 (pre-activation) ----
    gemm_64_f32x2(As, Bs, r0, col0, acc2);
    {
        float b0 = __ldg(bf1 + col0 + 0), b1 = __ldg(bf1 + col0 + 1);
        float b2 = __ldg(bf1 + col0 + 2), b3 = __ldg(bf1 + col0 + 3);
        #pragma unroll
        for (int i = 0; i < 8; i++) {
            int grow = row0 + r0 + i;
            if (grow < n) {
                float2 c01 = unpack2(acc2[i][0]);
                float2 c23 = unpack2(acc2[i][1]);
                float4 o;
                o.x = c01.x + b0;
                o.y = c01.y + b1;
                o.z = c23.x + b2;
                o.w = c23.y + b3;
                *(float4*)(g_xf + (size_t)grow * DD + col0) = o;
            }
        }
    }
}

// ---------------- edge kernel: warp per 4 edges ----------------
__global__ void __launch_bounds__(256) edge_kernel(
    const void* __restrict__ ei_raw, const float* __restrict__ pos,
    const float* __restrict__ Wf1, int E_)
{
    __shared__ float w[3 * DD];
    if (threadIdx.x < 128) {
        w[threadIdx.x]       = __ldg(Wf1 + threadIdx.x);
        w[128 + threadIdx.x] = __ldg(Wf1 + DD + threadIdx.x);
        w[256 + threadIdx.x] = __ldg(Wf1 + 2 * DD + threadIdx.x);
    }
    __syncthreads();

    const int lane = threadIdx.x & 31;
    const int c = lane << 2;
    // hoist this lane's 12 weights into registers
    float w0x = w[c], w0y = w[c+1], w0z = w[c+2], w0w = w[c+3];
    float w1x = w[128+c], w1y = w[128+c+1], w1z = w[128+c+2], w1w = w[128+c+3];
    float w2x = w[256+c], w2y = w[256+c+1], w2z = w[256+c+2], w2w = w[256+c+3];

    const int is64 = g_is64;
    int eBase = ((blockIdx.x << 3) + (threadIdx.x >> 5)) << 2;   // 4 edges per warp

    #pragma unroll
    for (int t = 0; t < 4; t++) {
        int e = eBase + t;
        if (e >= E_) break;

        int src, dst;
        if (is64) {
            const long long* ei = (const long long*)ei_raw;
            src = (int)__ldg(ei + e);
            dst = (int)__ldg(ei + (size_t)E_ + e);
        } else {
            const int* ei = (const int*)ei_raw;
            src = __ldg(ei + e);
            dst = __ldg(ei + (size_t)E_ + e);
        }

        float rv = 0.f;
        if (lane < 3)
            rv = __ldg(pos + src * 3 + lane) - __ldg(pos + dst * 3 + lane)
               + g_delta[dst * 3 + lane];
        float r0 = __shfl_sync(0xffffffffu, rv, 0);
        float r1 = __shfl_sync(0xffffffffu, rv, 1);
        float r2 = __shfl_sync(0xffffffffu, rv, 2);

        float4 xv = *(const float4*)(g_xf + (size_t)src * DD + c);
        float4 m;
        m.x = lrelu(fmaf(r0, w0x, fmaf(r1, w1x, fmaf(r2, w2x, xv.x))));
        m.y = lrelu(fmaf(r0, w0y, fmaf(r1, w1y, fmaf(r2, w2y, xv.y))));
        m.z = lrelu(fmaf(r0, w0z, fmaf(r1, w1z, fmaf(r2, w2z, xv.z))));
        m.w = lrelu(fmaf(r0, w0w, fmaf(r1, w1w, fmaf(r2, w2w, xv.w))));

        red_add_v4(g_aggr + (size_t)dst * DD + c, m);
    }
}

// ---------------- fused node post: out = x + leaky(aggr@Wg1+bg1)@Wg2 + bg2 ----------------
__global__ void __launch_bounds__(256) node_post(
    const float* __restrict__ x,
    const float* __restrict__ Wg1, const float* __restrict__ bg1,
    const float* __restrict__ Wg2, const float* __restrict__ bg2,
    float* __restrict__ out, int n)
{
    extern __shared__ float sm[];
    float* As = sm;                 // 64*ASR (row-major)
    float* Bs = sm + 64 * ASR;      // 128*128
    const int tid  = threadIdx.x;
    const int row0 = blockIdx.x * 64;

    // load aggr tile row-major (aligned device array -> float4 OK)
    {
        const int row = tid >> 2;
        const int cb  = (tid & 3) << 2;
        int grow = row0 + row; if (grow >= n) grow = n - 1;
        #pragma unroll
        for (int i = 0; i < 8; i++) {
            int col = cb + (i << 4);
            float4 v = *(const float4*)(g_aggr + (size_t)grow * DD + col);
            *(float4*)(As + row * ASR + col) = v;
        }
    }
    fill_w(Bs, Wg1, tid);
    __syncthreads();

    const int col0 = (tid & 31) << 2;
    const int r0   = (tid >> 5) << 3;

    unsigned long long acc2[8][2];
    gemm_64_f32x2(As, Bs, r0, col0, acc2);
    __syncthreads();   // done reading As/Bs before overwrite

    // t = leaky(acc + bg1) stored row-major back into As for GEMM2
    {
        float b0 = __ldg(bg1 + col0 + 0), b1 = __ldg(bg1 + col0 + 1);
        float b2 = __ldg(bg1 + col0 + 2), b3 = __ldg(bg1 + col0 + 3);
        #pragma unroll
        for (int i = 0; i < 8; i++) {
            float2 c01 = unpack2(acc2[i][0]);
            float2 c23 = unpack2(acc2[i][1]);
            float4 tv;
            tv.x = lrelu(c01.x + b0);
            tv.y = lrelu(c01.y + b1);
            tv.z = lrelu(c23.x + b2);
            tv.w = lrelu(c23.y + b3);
            *(float4*)(As + (r0 + i) * ASR + col0) = tv;   // aligned: ASR%4==0, col0%4==0
        }
    }
    fill_w(Bs, Wg2, tid);
    __syncthreads();

    gemm_64_f32x2(As, Bs, r0, col0, acc2);
    {
        float b0 = __ldg(bg2 + col0 + 0), b1 = __ldg(bg2 + col0 + 1);
        float b2 = __ldg(bg2 + col0 + 2), b3 = __ldg(bg2 + col0 + 3);
        #pragma unroll
        for (int i = 0; i < 8; i++) {
            int grow = row0 + r0 + i;
            if (grow < n) {
                float4 xv = *(const float4*)(x + (size_t)grow * DD + col0);
                float2 c01 = unpack2(acc2[i][0]);
                float2 c23 = unpack2(acc2[i][1]);
                float4 o;
                o.x = xv.x + c01.x + b0;
                o.y = xv.y + c01.y + b1;
                o.z = xv.z + c23.x + b2;
                o.w = xv.w + c23.y + b3;
                *(float4*)(out + (size_t)grow * DD + col0) = o;   // d_out: own allocation
            }
        }
    }
}

// ---------------- launch ----------------
extern "C" void kernel_launch(void* const* d_in, const int* in_sizes, int n_in,
                              void* d_out, int out_size)
{
    const float* x   = (const float*)d_in[0];
    const float* pos = (const float*)d_in[1];
    const void*  ei  = d_in[2];
    const float* Wh1 = (const float*)d_in[3];
    const float* bh1 = (const float*)d_in[4];
    const float* Wh2 = (const float*)d_in[5];
    const float* bh2 = (const float*)d_in[6];
    const float* Wf1 = (const float*)d_in[7];
    const float* bf1 = (const float*)d_in[8];
    const float* Wg1 = (const float*)d_in[9];
    const float* bg1 = (const float*)d_in[10];
    const float* Wg2 = (const float*)d_in[11];
    const float* bg2 = (const float*)d_in[12];
    float* out = (float*)d_out;

    const int n  = in_sizes[0] / DD;
    const int E_ = in_sizes[2] / 2;

    const int NODE_SMEM = (64 * ASR + 128 * 128) * (int)sizeof(float);   // ~97KB
    cudaFuncSetAttribute(node_pre,  cudaFuncAttributeMaxDynamicSharedMemorySize, NODE_SMEM);
    cudaFuncSetAttribute(node_post, cudaFuncAttributeMaxDynamicSharedMemorySize, NODE_SMEM);

    void* aggrPtr = nullptr;
    cudaGetSymbolAddress(&aggrPtr, g_aggr);
    cudaMemsetAsync(aggrPtr, 0, (size_t)n * DD * sizeof(float));

    detect_idx_kernel<<<1, 256>>>((const unsigned int*)ei, E_);

    const int gridN = (n + 63) / 64;
    node_pre<<<gridN, 256, NODE_SMEM>>>(x, Wh1, bh1, Wh2, bh2, Wf1, bf1, n);
    const int edgeBlocks = (E_ + 31) / 32;   // 8 warps * 4 edges per block
    edge_kernel<<<edgeBlocks, 256>>>(ei, pos, Wf1, E_);
    node_post<<<gridN, 256, NODE_SMEM>>>(x, Wg1, bg1, Wg2, bg2, out, n);
}

// round 8
// speedup vs baseline: 1.2133x; 1.0241x over previous
#include <cuda_runtime.h>

#define DD 128
#define NMAX 40000
#define ASR 132   // row-major A tile stride: 132*4=528 bytes, 16B-aligned float4 rows

// ---------------- device scratch (no allocs allowed), 16B-aligned ----------------
__device__ __align__(16) float g_delta[(size_t)NMAX * 3];
__device__ __align__(16) float g_xf[(size_t)NMAX * DD];
__device__ __align__(16) float g_aggr[(size_t)NMAX * DD];
__device__ int   g_is64;

__device__ __forceinline__ float lrelu(float v) { return v >= 0.f ? v : 0.01f * v; }

__device__ __forceinline__ void red_add_v4(float* addr, float4 v) {
    asm volatile("red.global.add.v4.f32 [%0], {%1,%2,%3,%4};"
                 :: "l"(addr), "f"(v.x), "f"(v.y), "f"(v.z), "f"(v.w) : "memory");
}

// packed f32x2 helpers (Blackwell FFMA2 path)
__device__ __forceinline__ unsigned long long pack2(float v) {
    unsigned long long r;
    asm("mov.b64 %0, {%1, %1};" : "=l"(r) : "f"(v));
    return r;
}
__device__ __forceinline__ void ffma2(unsigned long long& d, unsigned long long a,
                                      unsigned long long b) {
    asm("fma.rn.f32x2 %0, %1, %2, %0;" : "+l"(d) : "l"(a), "l"(b));
}
__device__ __forceinline__ float2 unpack2(unsigned long long u) {
    float2 f;
    asm("mov.b64 {%0, %1}, %2;" : "=f"(f.x), "=f"(f.y) : "l"(u));
    return f;
}

// scalar (4B-safe) smem fill of a 64x128 half weight tile, 256 threads
__device__ __forceinline__ void fill_w_half(float* Bs, const float* __restrict__ W, int tid) {
    #pragma unroll
    for (int i = 0; i < 32; i++) Bs[tid + (i << 8)] = __ldg(W + tid + (i << 8));
}

// ---------------- edge_index dtype sniffer ----------------
__global__ void detect_idx_kernel(const unsigned int* ei32, int E_) {
    __shared__ int ok;
    if (threadIdx.x == 0) ok = 1;
    __syncthreads();
    if (E_ > 0) {
        long long stride = (long long)E_ / 256;
        if (stride < 1) stride = 1;
        long long i = (long long)threadIdx.x * stride;   // i < E_
        if (i < E_) {
            unsigned int hi = ei32[2 * i + 1];
            if (hi != 0) ok = 0;
        }
    }
    __syncthreads();
    if (threadIdx.x == 0) g_is64 = ok;
}

// half-K (64) GEMM accumulate: A row-major [64][ASR] at column offset aOff (float4
// broadcast loads), B half tile [64][128] (ulonglong2 loads), FFMA2 accumulation.
__device__ __forceinline__ void gemm_half_f32x2(const float* __restrict__ As,
                                                const float* __restrict__ Bs,
                                                int r0, int col0, int aOff,
                                                unsigned long long acc2[8][2]) {
    #pragma unroll 4
    for (int kk = 0; kk < 64; kk += 4) {
        ulonglong2 b[4];
        #pragma unroll
        for (int j = 0; j < 4; j++)
            b[j] = *(const ulonglong2*)(Bs + (kk + j) * 128 + col0);   // 16B-aligned
        #pragma unroll
        for (int i = 0; i < 8; i++) {
            float4 av = *(const float4*)(As + (r0 + i) * ASR + aOff + kk); // broadcast, aligned
            unsigned long long a0 = pack2(av.x), a1 = pack2(av.y);
            unsigned long long a2 = pack2(av.z), a3 = pack2(av.w);
            ffma2(acc2[i][0], a0, b[0].x); ffma2(acc2[i][1], a0, b[0].y);
            ffma2(acc2[i][0], a1, b[1].x); ffma2(acc2[i][1], a1, b[1].y);
            ffma2(acc2[i][0], a2, b[2].x); ffma2(acc2[i][1], a2, b[2].y);
            ffma2(acc2[i][0], a3, b[3].x); ffma2(acc2[i][1], a3, b[3].y);
        }
    }
}

__device__ __forceinline__ void zero_acc(unsigned long long acc2[8][2]) {
    #pragma unroll
    for (int i = 0; i < 8; i++) { acc2[i][0] = 0ull; acc2[i][1] = 0ull; }
}

// full GEMM = two half-K passes with B refills (keeps smem at 65KB -> 3 CTAs/SM)
__device__ __forceinline__ void gemm_2pass(const float* As, float* Bs,
                                           const float* __restrict__ W,
                                           int tid, int r0, int col0,
                                           unsigned long long acc2[8][2]) {
    zero_acc(acc2);
    fill_w_half(Bs, W, tid);
    __syncthreads();
    gemm_half_f32x2(As, Bs, r0, col0, 0, acc2);
    __syncthreads();
    fill_w_half(Bs, W + 64 * DD, tid);
    __syncthreads();
    gemm_half_f32x2(As, Bs, r0, col0, 64, acc2);
}

// ---------------- fused node precompute: h, delta, xf ----------------
// smem: As[64][ASR] (row-major x tile, 33.8KB) + Bs[64][128] (half weights, 32KB)
__global__ void __launch_bounds__(256, 3) node_pre(
    const float* __restrict__ x,
    const float* __restrict__ Wh1, const float* __restrict__ bh1,
    const float* __restrict__ Wh2, const float* __restrict__ bh2,
    const float* __restrict__ Wf1, const float* __restrict__ bf1,
    int n)
{
    extern __shared__ float sm[];
    float* As = sm;                 // 64*ASR
    float* Bs = sm + 64 * ASR;      // 64*128
    const int tid  = threadIdx.x;
    const int row0 = blockIdx.x * 64;

    // load x tile row-major (x = d_in[0], base-aligned -> float4 OK)
    {
        const int row = tid >> 2;
        const int cb  = (tid & 3) << 2;
        int grow = row0 + row; if (grow >= n) grow = n - 1;
        #pragma unroll
        for (int i = 0; i < 8; i++) {
            int col = cb + (i << 4);
            *(float4*)(As + row * ASR + col) = *(const float4*)(x + (size_t)grow * DD + col);
        }
    }
    __syncthreads();

    const int col0 = (tid & 31) << 2;
    const int r0   = (tid >> 5) << 3;
    const int lane = tid & 31;

    // ---- GEMM1: h = leaky(x @ Wh1 + bh1), consumed immediately by the delta head ----
    unsigned long long acc2[8][2];
    gemm_2pass(As, Bs, Wh1, tid, r0, col0, acc2);

    // delta head: partial h·Wh2 per thread, butterfly-reduce across warp (cols), no smem
    {
        float b0 = __ldg(bh1 + col0 + 0), b1 = __ldg(bh1 + col0 + 1);
        float b2 = __ldg(bh1 + col0 + 2), b3 = __ldg(bh1 + col0 + 3);
        // this lane's 4 columns of Wh2 (rows col0..col0+3, 3 comps each)
        float w2[4][3];
        #pragma unroll
        for (int j = 0; j < 4; j++)
            #pragma unroll
            for (int c = 0; c < 3; c++) w2[j][c] = __ldg(Wh2 + (col0 + j) * 3 + c);

        float d[8][3];
        #pragma unroll
        for (int i = 0; i < 8; i++) {
            float2 c01 = unpack2(acc2[i][0]);
            float2 c23 = unpack2(acc2[i][1]);
            float h0 = lrelu(c01.x + b0);
            float h1 = lrelu(c01.y + b1);
            float h2 = lrelu(c23.x + b2);
            float h3 = lrelu(c23.y + b3);
            #pragma unroll
            for (int c = 0; c < 3; c++)
                d[i][c] = fmaf(h0, w2[0][c], fmaf(h1, w2[1][c],
                          fmaf(h2, w2[2][c], h3 * w2[3][c])));
        }
        #pragma unroll
        for (int off = 16; off >= 1; off >>= 1)
            #pragma unroll
            for (int i = 0; i < 8; i++)
                #pragma unroll
                for (int c = 0; c < 3; c++)
                    d[i][c] += __shfl_xor_sync(0xffffffffu, d[i][c], off);
        if (lane == 0) {
            float bb0 = __ldg(bh2 + 0), bb1 = __ldg(bh2 + 1), bb2 = __ldg(bh2 + 2);
            #pragma unroll
            for (int i = 0; i < 8; i++) {
                int grow = row0 + r0 + i;
                if (grow < n) {
                    g_delta[(size_t)grow * 3 + 0] = tanhf(d[i][0] + bb0);
                    g_delta[(size_t)grow * 3 + 1] = tanhf(d[i][1] + bb1);
                    g_delta[(size_t)grow * 3 + 2] = tanhf(d[i][2] + bb2);
                }
            }
        }
    }
    __syncthreads();

    // ---- GEMM2: xf = x @ Wf1[3:] + bf1 (pre-activation) ----
    gemm_2pass(As, Bs, Wf1 + 3 * DD, tid, r0, col0, acc2);
    {
        float b0 = __ldg(bf1 + col0 + 0), b1 = __ldg(bf1 + col0 + 1);
        float b2 = __ldg(bf1 + col0 + 2), b3 = __ldg(bf1 + col0 + 3);
        #pragma unroll
        for (int i = 0; i < 8; i++) {
            int grow = row0 + r0 + i;
            if (grow < n) {
                float2 c01 = unpack2(acc2[i][0]);
                float2 c23 = unpack2(acc2[i][1]);
                float4 o;
                o.x = c01.x + b0;
                o.y = c01.y + b1;
                o.z = c23.x + b2;
                o.w = c23.y + b3;
                *(float4*)(g_xf + (size_t)grow * DD + col0) = o;
            }
        }
    }
}

// ---------------- edge kernel: warp per 4 edges ----------------
__global__ void __launch_bounds__(256) edge_kernel(
    const void* __restrict__ ei_raw, const float* __restrict__ pos,
    const float* __restrict__ Wf1, int E_)
{
    __shared__ float w[3 * DD];
    if (threadIdx.x < 128) {
        w[threadIdx.x]       = __ldg(Wf1 + threadIdx.x);
        w[128 + threadIdx.x] = __ldg(Wf1 + DD + threadIdx.x);
        w[256 + threadIdx.x] = __ldg(Wf1 + 2 * DD + threadIdx.x);
    }
    __syncthreads();

    const int lane = threadIdx.x & 31;
    const int c = lane << 2;
    float w0x = w[c], w0y = w[c+1], w0z = w[c+2], w0w = w[c+3];
    float w1x = w[128+c], w1y = w[128+c+1], w1z = w[128+c+2], w1w = w[128+c+3];
    float w2x = w[256+c], w2y = w[256+c+1], w2z = w[256+c+2], w2w = w[256+c+3];

    const int is64 = g_is64;
    int eBase = ((blockIdx.x << 3) + (threadIdx.x >> 5)) << 2;   // 4 edges per warp

    #pragma unroll
    for (int t = 0; t < 4; t++) {
        int e = eBase + t;
        if (e >= E_) break;

        int src, dst;
        if (is64) {
            const long long* ei = (const long long*)ei_raw;
            src = (int)__ldg(ei + e);
            dst = (int)__ldg(ei + (size_t)E_ + e);
        } else {
            const int* ei = (const int*)ei_raw;
            src = __ldg(ei + e);
            dst = __ldg(ei + (size_t)E_ + e);
        }

        float rv = 0.f;
        if (lane < 3)
            rv = __ldg(pos + src * 3 + lane) - __ldg(pos + dst * 3 + lane)
               + g_delta[dst * 3 + lane];
        float r0 = __shfl_sync(0xffffffffu, rv, 0);
        float r1 = __shfl_sync(0xffffffffu, rv, 1);
        float r2 = __shfl_sync(0xffffffffu, rv, 2);

        float4 xv = *(const float4*)(g_xf + (size_t)src * DD + c);
        float4 m;
        m.x = lrelu(fmaf(r0, w0x, fmaf(r1, w1x, fmaf(r2, w2x, xv.x))));
        m.y = lrelu(fmaf(r0, w0y, fmaf(r1, w1y, fmaf(r2, w2y, xv.y))));
        m.z = lrelu(fmaf(r0, w0z, fmaf(r1, w1z, fmaf(r2, w2z, xv.z))));
        m.w = lrelu(fmaf(r0, w0w, fmaf(r1, w1w, fmaf(r2, w2w, xv.w))));

        red_add_v4(g_aggr + (size_t)dst * DD + c, m);
    }
}

// ---------------- fused node post: out = x + leaky(aggr@Wg1+bg1)@Wg2 + bg2 ----------------
__global__ void __launch_bounds__(256, 3) node_post(
    const float* __restrict__ x,
    const float* __restrict__ Wg1, const float* __restrict__ bg1,
    const float* __restrict__ Wg2, const float* __restrict__ bg2,
    float* __restrict__ out, int n)
{
    extern __shared__ float sm[];
    float* As = sm;                 // 64*ASR (row-major)
    float* Bs = sm + 64 * ASR;      // 64*128
    const int tid  = threadIdx.x;
    const int row0 = blockIdx.x * 64;

    // load aggr tile row-major (aligned device array -> float4 OK)
    {
        const int row = tid >> 2;
        const int cb  = (tid & 3) << 2;
        int grow = row0 + row; if (grow >= n) grow = n - 1;
        #pragma unroll
        for (int i = 0; i < 8; i++) {
            int col = cb + (i << 4);
            *(float4*)(As + row * ASR + col) =
                *(const float4*)(g_aggr + (size_t)grow * DD + col);
        }
    }
    __syncthreads();

    const int col0 = (tid & 31) << 2;
    const int r0   = (tid >> 5) << 3;

    unsigned long long acc2[8][2];
    gemm_2pass(As, Bs, Wg1, tid, r0, col0, acc2);
    __syncthreads();   // done reading As before overwrite

    // t = leaky(acc + bg1) stored row-major back into As for GEMM2
    {
        float b0 = __ldg(bg1 + col0 + 0), b1 = __ldg(bg1 + col0 + 1);
        float b2 = __ldg(bg1 + col0 + 2), b3 = __ldg(bg1 + col0 + 3);
        #pragma unroll
        for (int i = 0; i < 8; i++) {
            float2 c01 = unpack2(acc2[i][0]);
            float2 c23 = unpack2(acc2[i][1]);
            float4 tv;
            tv.x = lrelu(c01.x + b0);
            tv.y = lrelu(c01.y + b1);
            tv.z = lrelu(c23.x + b2);
            tv.w = lrelu(c23.y + b3);
            *(float4*)(As + (r0 + i) * ASR + col0) = tv;
        }
    }
    __syncthreads();

    gemm_2pass(As, Bs, Wg2, tid, r0, col0, acc2);
    {
        float b0 = __ldg(bg2 + col0 + 0), b1 = __ldg(bg2 + col0 + 1);
        float b2 = __ldg(bg2 + col0 + 2), b3 = __ldg(bg2 + col0 + 3);
        #pragma unroll
        for (int i = 0; i < 8; i++) {
            int grow = row0 + r0 + i;
            if (grow < n) {
                float4 xv = *(const float4*)(x + (size_t)grow * DD + col0);
                float2 c01 = unpack2(acc2[i][0]);
                float2 c23 = unpack2(acc2[i][1]);
                float4 o;
                o.x = xv.x + c01.x + b0;
                o.y = xv.y + c01.y + b1;
                o.z = xv.z + c23.x + b2;
                o.w = xv.w + c23.y + b3;
                *(float4*)(out + (size_t)grow * DD + col0) = o;
            }
        }
    }
}

// ---------------- launch ----------------
extern "C" void kernel_launch(void* const* d_in, const int* in_sizes, int n_in,
                              void* d_out, int out_size)
{
    const float* x   = (const float*)d_in[0];
    const float* pos = (const float*)d_in[1];
    const void*  ei  = d_in[2];
    const float* Wh1 = (const float*)d_in[3];
    const float* bh1 = (const float*)d_in[4];
    const float* Wh2 = (const float*)d_in[5];
    const float* bh2 = (const float*)d_in[6];
    const float* Wf1 = (const float*)d_in[7];
    const float* bf1 = (const float*)d_in[8];
    const float* Wg1 = (const float*)d_in[9];
    const float* bg1 = (const float*)d_in[10];
    const float* Wg2 = (const float*)d_in[11];
    const float* bg2 = (const float*)d_in[12];
    float* out = (float*)d_out;

    const int n  = in_sizes[0] / DD;
    const int E_ = in_sizes[2] / 2;

    const int NODE_SMEM = (64 * ASR + 64 * DD) * (int)sizeof(float);   // ~65KB -> 3 CTAs/SM
    cudaFuncSetAttribute(node_pre,  cudaFuncAttributeMaxDynamicSharedMemorySize, NODE_SMEM);
    cudaFuncSetAttribute(node_post, cudaFuncAttributeMaxDynamicSharedMemorySize, NODE_SMEM);

    void* aggrPtr = nullptr;
    cudaGetSymbolAddress(&aggrPtr, g_aggr);
    cudaMemsetAsync(aggrPtr, 0, (size_t)n * DD * sizeof(float));

    detect_idx_kernel<<<1, 256>>>((const unsigned int*)ei, E_);

    const int gridN = (n + 63) / 64;
    node_pre<<<gridN, 256, NODE_SMEM>>>(x, Wh1, bh1, Wh2, bh2, Wf1, bf1, n);
    const int edgeBlocks = (E_ + 31) / 32;   // 8 warps * 4 edges per block
    edge_kernel<<<edgeBlocks, 256>>>(ei, pos, Wf1, E_);
    node_post<<<gridN, 256, NODE_SMEM>>>(x, Wg1, bg1, Wg2, bg2, out, n);
}

// round 11
// speedup vs baseline: 1.2391x; 1.0213x over previous
#include <cuda_runtime.h>

#define DD 128
#define NMAX 40000
#define ASR 132   // A tile stride (floats): 132*4B, float4-aligned rows, conflict-free frags
#define BSR 132   // W tile stride

// ---------------- device scratch (no allocs allowed), 16B-aligned ----------------
__device__ __align__(16) float g_delta[(size_t)NMAX * 3];
__device__ __align__(16) float g_xf[(size_t)NMAX * DD];
__device__ __align__(16) float g_aggr[(size_t)NMAX * DD];
__device__ int   g_is64;

__device__ __forceinline__ float lrelu(float v) { return v >= 0.f ? v : 0.01f * v; }

__device__ __forceinline__ void red_add_v4(float* addr, float4 v) {
    asm volatile("red.global.add.v4.f32 [%0], {%1,%2,%3,%4};"
                 :: "l"(addr), "f"(v.x), "f"(v.y), "f"(v.z), "f"(v.w) : "memory");
}

// ---------------- tf32 mma helpers ----------------
__device__ __forceinline__ unsigned cvt_tf32(float v) {
    unsigned r; asm("cvt.rna.tf32.f32 %0, %1;" : "=r"(r) : "f"(v)); return r;
}
__device__ __forceinline__ void mma_tf32(float d[4], const unsigned a[4],
                                         unsigned b0, unsigned b1) {
    asm("mma.sync.aligned.m16n8k8.row.col.f32.tf32.tf32.f32 "
        "{%0,%1,%2,%3}, {%4,%5,%6,%7}, {%8,%9}, {%0,%1,%2,%3};"
        : "+f"(d[0]), "+f"(d[1]), "+f"(d[2]), "+f"(d[3])
        : "r"(a[0]), "r"(a[1]), "r"(a[2]), "r"(a[3]), "r"(b0), "r"(b1));
}

// Warp-tiled 3xTF32 GEMM: warp computes rows [rw, rw+32) x cols [cw, cw+32)
// As: [64][ASR] row-major fp32; Ws: [128][BSR] row-major (k x n) fp32.
// acc[m][j][r]: m in {0,1} (m16 blocks), j in {0..3} (n8 tiles), r per mma layout:
//   row = rw + 16m + gid + 8*(r>>1), col = cw + 8j + 2*tig + (r&1)
__device__ __forceinline__ void gemm_warp(const float* __restrict__ As,
                                          const float* __restrict__ Ws,
                                          int rw, int cw, int lane,
                                          float acc[2][4][4]) {
    const int gid = lane >> 2, tig = lane & 3;
    #pragma unroll
    for (int m = 0; m < 2; m++)
        #pragma unroll
        for (int j = 0; j < 4; j++)
            #pragma unroll
            for (int r = 0; r < 4; r++) acc[m][j][r] = 0.f;

    #pragma unroll 2
    for (int k0 = 0; k0 < 128; k0 += 8) {
        unsigned ah[2][4], al[2][4];
        #pragma unroll
        for (int m = 0; m < 2; m++) {
            const float* ap = As + (rw + 16 * m + gid) * ASR + k0 + tig;
            float a0 = ap[0];
            float a1 = ap[8 * ASR];
            float a2 = ap[4];
            float a3 = ap[8 * ASR + 4];
            ah[m][0] = cvt_tf32(a0); al[m][0] = cvt_tf32(a0 - __uint_as_float(ah[m][0]));
            ah[m][1] = cvt_tf32(a1); al[m][1] = cvt_tf32(a1 - __uint_as_float(ah[m][1]));
            ah[m][2] = cvt_tf32(a2); al[m][2] = cvt_tf32(a2 - __uint_as_float(ah[m][2]));
            ah[m][3] = cvt_tf32(a3); al[m][3] = cvt_tf32(a3 - __uint_as_float(ah[m][3]));
        }
        #pragma unroll
        for (int j = 0; j < 4; j++) {
            const float* bp = Ws + (k0 + tig) * BSR + cw + 8 * j + gid;
            float b0f = bp[0];
            float b1f = bp[4 * BSR];
            unsigned bh0 = cvt_tf32(b0f), bl0 = cvt_tf32(b0f - __uint_as_float(bh0));
            unsigned bh1 = cvt_tf32(b1f), bl1 = cvt_tf32(b1f - __uint_as_float(bh1));
            #pragma unroll
            for (int m = 0; m < 2; m++) {
                mma_tf32(acc[m][j], ah[m], bh0, bh1);
                mma_tf32(acc[m][j], al[m], bh0, bh1);
                mma_tf32(acc[m][j], ah[m], bl0, bl1);
            }
        }
    }
}

// scalar smem fill of a 128x128 weight into [128][BSR]
__device__ __forceinline__ void fill_ws(float* Ws, const float* __restrict__ W, int tid) {
    #pragma unroll
    for (int i = 0; i < 64; i++) {
        int idx = tid + (i << 8);
        Ws[(idx >> 7) * BSR + (idx & 127)] = __ldg(W + idx);
    }
}

// ---------------- edge_index dtype sniffer ----------------
__global__ void detect_idx_kernel(const unsigned int* ei32, int E_) {
    __shared__ int ok;
    if (threadIdx.x == 0) ok = 1;
    __syncthreads();
    if (E_ > 0) {
        long long stride = (long long)E_ / 256;
        if (stride < 1) stride = 1;
        long long i = (long long)threadIdx.x * stride;
        if (i < E_) {
            unsigned int hi = ei32[2 * i + 1];
            if (hi != 0) ok = 0;
        }
    }
    __syncthreads();
    if (threadIdx.x == 0) g_is64 = ok;
}

// ---------------- fused node precompute: h, delta, xf ----------------
// smem: As[64][ASR] | Ws[128][BSR] | wh2s[384] | b1s[128] | b2s[128] | dpart[192]
__global__ void __launch_bounds__(256, 2) node_pre(
    const float* __restrict__ x,
    const float* __restrict__ Wh1, const float* __restrict__ bh1,
    const float* __restrict__ Wh2, const float* __restrict__ bh2,
    const float* __restrict__ Wf1, const float* __restrict__ bf1,
    int n)
{
    extern __shared__ float sm[];
    float* As    = sm;
    float* Ws    = sm + 64 * ASR;
    float* wh2s  = Ws + 128 * BSR;
    float* b1s   = wh2s + 384;
    float* b2s   = b1s + 128;
    float* dpart = b2s + 128;
    const int tid  = threadIdx.x;
    const int row0 = blockIdx.x * 64;

    // fills
    {
        const int row = tid >> 2;
        const int cb  = (tid & 3) << 2;
        int grow = row0 + row; if (grow >= n) grow = n - 1;
        #pragma unroll
        for (int i = 0; i < 8; i++) {
            int col = cb + (i << 4);
            *(float4*)(As + row * ASR + col) = *(const float4*)(x + (size_t)grow * DD + col);
        }
    }
    fill_ws(Ws, Wh1, tid);
    if (tid < 192) {
        wh2s[tid]       = __ldg(Wh2 + tid);
        wh2s[tid + 192] = __ldg(Wh2 + tid + 192);
        dpart[tid] = 0.f;
    }
    if (tid < 128) {
        b1s[tid] = __ldg(bh1 + tid);
        b2s[tid] = __ldg(bf1 + tid);
    }
    __syncthreads();

    const int wid  = tid >> 5, lane = tid & 31;
    const int gid  = lane >> 2, tig = lane & 3;
    const int rw   = (wid & 1) * 32;
    const int cw   = (wid >> 1) * 32;

    // ---- GEMM1: h = leaky(x @ Wh1 + bh1) -> delta head ----
    float acc[2][4][4];
    gemm_warp(As, Ws, rw, cw, lane, acc);

    {
        float d[2][2][3];
        #pragma unroll
        for (int m = 0; m < 2; m++)
            #pragma unroll
            for (int rh = 0; rh < 2; rh++)
                #pragma unroll
                for (int c = 0; c < 3; c++) d[m][rh][c] = 0.f;

        #pragma unroll
        for (int m = 0; m < 2; m++)
            #pragma unroll
            for (int j = 0; j < 4; j++)
                #pragma unroll
                for (int r = 0; r < 4; r++) {
                    int col = cw + 8 * j + 2 * tig + (r & 1);
                    int rh  = r >> 1;
                    float h = lrelu(acc[m][j][r] + b1s[col]);
                    const float* w2 = wh2s + col * 3;
                    d[m][rh][0] = fmaf(h, w2[0], d[m][rh][0]);
                    d[m][rh][1] = fmaf(h, w2[1], d[m][rh][1]);
                    d[m][rh][2] = fmaf(h, w2[2], d[m][rh][2]);
                }
        #pragma unroll
        for (int m = 0; m < 2; m++)
            #pragma unroll
            for (int rh = 0; rh < 2; rh++) {
                int lrow = rw + 16 * m + 8 * rh + gid;
                atomicAdd(&dpart[lrow * 3 + 0], d[m][rh][0]);
                atomicAdd(&dpart[lrow * 3 + 1], d[m][rh][1]);
                atomicAdd(&dpart[lrow * 3 + 2], d[m][rh][2]);
            }
    }
    __syncthreads();

    if (tid < 192) {
        int lrow = tid / 3, c = tid - lrow * 3;
        int grow = row0 + lrow;
        if (grow < n)
            g_delta[(size_t)grow * 3 + c] = tanhf(dpart[tid] + __ldg(bh2 + c));
    }
    __syncthreads();

    // refill Ws with Wf1 rows 3..130
    fill_ws(Ws, Wf1 + 3 * DD, tid);
    __syncthreads();

    // ---- GEMM2: xf = x @ Wf1[3:] + bf1 ----
    gemm_warp(As, Ws, rw, cw, lane, acc);
    #pragma unroll
    for (int m = 0; m < 2; m++)
        #pragma unroll
        for (int j = 0; j < 4; j++)
            #pragma unroll
            for (int rh = 0; rh < 2; rh++) {
                int row  = rw + 16 * m + 8 * rh + gid;
                int col  = cw + 8 * j + 2 * tig;
                int grow = row0 + row;
                float2 v;
                v.x = acc[m][j][2 * rh + 0] + b2s[col];
                v.y = acc[m][j][2 * rh + 1] + b2s[col + 1];
                *(float2*)(g_xf + (size_t)grow * DD + col) = v;
            }
}

// ---------------- edge kernel: warp per 4 edges ----------------
__global__ void __launch_bounds__(256) edge_kernel(
    const void* __restrict__ ei_raw, const float* __restrict__ pos,
    const float* __restrict__ Wf1, int E_)
{
    __shared__ float w[3 * DD];
    if (threadIdx.x < 128) {
        w[threadIdx.x]       = __ldg(Wf1 + threadIdx.x);
        w[128 + threadIdx.x] = __ldg(Wf1 + DD + threadIdx.x);
        w[256 + threadIdx.x] = __ldg(Wf1 + 2 * DD + threadIdx.x);
    }
    __syncthreads();

    const int lane = threadIdx.x & 31;
    const int c = lane << 2;
    float w0x = w[c], w0y = w[c+1], w0z = w[c+2], w0w = w[c+3];
    float w1x = w[128+c], w1y = w[128+c+1], w1z = w[128+c+2], w1w = w[128+c+3];
    float w2x = w[256+c], w2y = w[256+c+1], w2z = w[256+c+2], w2w = w[256+c+3];

    const int is64 = g_is64;
    int eBase = ((blockIdx.x << 3) + (threadIdx.x >> 5)) << 2;

    #pragma unroll
    for (int t = 0; t < 4; t++) {
        int e = eBase + t;
        if (e >= E_) break;

        int src, dst;
        if (is64) {
            const long long* ei = (const long long*)ei_raw;
            src = (int)__ldg(ei + e);
            dst = (int)__ldg(ei + (size_t)E_ + e);
        } else {
            const int* ei = (const int*)ei_raw;
            src = __ldg(ei + e);
            dst = __ldg(ei + (size_t)E_ + e);
        }

        float rv = 0.f;
        if (lane < 3)
            rv = __ldg(pos + src * 3 + lane) - __ldg(pos + dst * 3 + lane)
               + g_delta[dst * 3 + lane];
        float r0 = __shfl_sync(0xffffffffu, rv, 0);
        float r1 = __shfl_sync(0xffffffffu, rv, 1);
        float r2 = __shfl_sync(0xffffffffu, rv, 2);

        float4 xv = *(const float4*)(g_xf + (size_t)src * DD + c);
        float4 m;
        m.x = lrelu(fmaf(r0, w0x, fmaf(r1, w1x, fmaf(r2, w2x, xv.x))));
        m.y = lrelu(fmaf(r0, w0y, fmaf(r1, w1y, fmaf(r2, w2y, xv.y))));
        m.z = lrelu(fmaf(r0, w0z, fmaf(r1, w1z, fmaf(r2, w2z, xv.z))));
        m.w = lrelu(fmaf(r0, w0w, fmaf(r1, w1w, fmaf(r2, w2w, xv.w))));

        red_add_v4(g_aggr + (size_t)dst * DD + c, m);
    }
}

// ---------------- fused node post: out = x + leaky(aggr@Wg1+bg1)@Wg2 + bg2 ----------------
// smem: As[64][ASR] | Ws[128][BSR] | b1s[128] | b2s[128]
__global__ void __launch_bounds__(256, 2) node_post(
    const float* __restrict__ x,
    const float* __restrict__ Wg1, const float* __restrict__ bg1,
    const float* __restrict__ Wg2, const float* __restrict__ bg2,
    float* __restrict__ out, int n)
{
    extern __shared__ float sm[];
    float* As  = sm;
    float* Ws  = sm + 64 * ASR;
    float* b1s = Ws + 128 * BSR;
    float* b2s = b1s + 128;
    const int tid  = threadIdx.x;
    const int row0 = blockIdx.x * 64;

    {
        const int row = tid >> 2;
        const int cb  = (tid & 3) << 2;
        int grow = row0 + row; if (grow >= n) grow = n - 1;
        #pragma unroll
        for (int i = 0; i < 8; i++) {
            int col = cb + (i << 4);
            *(float4*)(As + row * ASR + col) =
                *(const float4*)(g_aggr + (size_t)grow * DD + col);
        }
    }
    fill_ws(Ws, Wg1, tid);
    if (tid < 128) {
        b1s[tid] = __ldg(bg1 + tid);
        b2s[tid] = __ldg(bg2 + tid);
    }
    __syncthreads();

    const int wid  = tid >> 5, lane = tid & 31;
    const int gid  = lane >> 2, tig = lane & 3;
    const int rw   = (wid & 1) * 32;
    const int cw   = (wid >> 1) * 32;

    float acc[2][4][4];
    gemm_warp(As, Ws, rw, cw, lane, acc);
    __syncthreads();   // all warps done reading As (GEMM1) and Ws

    // t = leaky(acc + bg1) written back into As; refill Ws with Wg2
    #pragma unroll
    for (int m = 0; m < 2; m++)
        #pragma unroll
        for (int j = 0; j < 4; j++)
            #pragma unroll
            for (int rh = 0; rh < 2; rh++) {
                int row = rw + 16 * m + 8 * rh + gid;
                int col = cw + 8 * j + 2 * tig;
                As[row * ASR + col]     = lrelu(acc[m][j][2 * rh + 0] + b1s[col]);
                As[row * ASR + col + 1] = lrelu(acc[m][j][2 * rh + 1] + b1s[col + 1]);
            }
    fill_ws(Ws, Wg2, tid);
    __syncthreads();

    gemm_warp(As, Ws, rw, cw, lane, acc);
    #pragma unroll
    for (int m = 0; m < 2; m++)
        #pragma unroll
        for (int j = 0; j < 4; j++)
            #pragma unroll
            for (int rh = 0; rh < 2; rh++) {
                int row  = rw + 16 * m + 8 * rh + gid;
                int col  = cw + 8 * j + 2 * tig;
                int grow = row0 + row;
                float2 xv = *(const float2*)(x + (size_t)grow * DD + col);
                float2 o;
                o.x = xv.x + acc[m][j][2 * rh + 0] + b2s[col];
                o.y = xv.y + acc[m][j][2 * rh + 1] + b2s[col + 1];
                *(float2*)(out + (size_t)grow * DD + col) = o;
            }
}

// ---------------- launch ----------------
extern "C" void kernel_launch(void* const* d_in, const int* in_sizes, int n_in,
                              void* d_out, int out_size)
{
    const float* x   = (const float*)d_in[0];
    const float* pos = (const float*)d_in[1];
    const void*  ei  = d_in[2];
    const float* Wh1 = (const float*)d_in[3];
    const float* bh1 = (const float*)d_in[4];
    const float* Wh2 = (const float*)d_in[5];
    const float* bh2 = (const float*)d_in[6];
    const float* Wf1 = (const float*)d_in[7];
    const float* bf1 = (const float*)d_in[8];
    const float* Wg1 = (const float*)d_in[9];
    const float* bg1 = (const float*)d_in[10];
    const float* Wg2 = (const float*)d_in[11];
    const float* bg2 = (const float*)d_in[12];
    float* out = (float*)d_out;

    const int n  = in_sizes[0] / DD;
    const int E_ = in_sizes[2] / 2;

    const int PRE_SMEM  = (64 * ASR + 128 * BSR + 384 + 128 + 128 + 192) * (int)sizeof(float);
    const int POST_SMEM = (64 * ASR + 128 * BSR + 128 + 128) * (int)sizeof(float);
    cudaFuncSetAttribute(node_pre,  cudaFuncAttributeMaxDynamicSharedMemorySize, PRE_SMEM);
    cudaFuncSetAttribute(node_post, cudaFuncAttributeMaxDynamicSharedMemorySize, POST_SMEM);

    void* aggrPtr = nullptr;
    cudaGetSymbolAddress(&aggrPtr, g_aggr);
    cudaMemsetAsync(aggrPtr, 0, (size_t)n * DD * sizeof(float));

    detect_idx_kernel<<<1, 256>>>((const unsigned int*)ei, E_);

    const int gridN = (n + 63) / 64;
    node_pre<<<gridN, 256, PRE_SMEM>>>(x, Wh1, bh1, Wh2, bh2, Wf1, bf1, n);
    const int edgeBlocks = (E_ + 31) / 32;
    edge_kernel<<<edgeBlocks, 256>>>(ei, pos, Wf1, E_);
    node_post<<<gridN, 256, POST_SMEM>>>(x, Wg1, bg1, Wg2, bg2, out, n);
}